// round 5
// baseline (speedup 1.0000x reference)
#include <cuda_runtime.h>
#include <math.h>

#define NB 4
#define NS 256
#define NV 1280
#define NH 128
#define EPSV 1e-5f
#define NROWS (NB*NS)   // 1024

// ---------------- scratch (no allocation allowed) ----------------
__device__ float g_q [NB*NS*NH];
__device__ float g_kT[NB*NH*NS];
__device__ float g_Xn[NB*NS*NV];
__device__ float g_h [NB*NS*NH];
__device__ float g_X2[NB*NS*NV];

// ---------------- tiled SGEMM: C[M,N] = A[M,K] @ W[K,N] ----------------
// BM=64, BN=32, BK=16, 256 threads, each thread 4x2 outputs.
// TRANS_OUT: write k transposed as [b, n(=h), j] with m = b*256 + j (N must be 128).
template<bool BIAS_RELU, bool TRANS_OUT>
__global__ void gemm_kernel(const float* __restrict__ A, const float* __restrict__ W,
                            const float* __restrict__ bias, float* __restrict__ C,
                            int M, int N, int K) {
    __shared__ float As[16][65];
    __shared__ float Bs[16][32];
    const int tid = threadIdx.x;
    const int tx = tid & 15;      // 0..15
    const int ty = tid >> 4;      // 0..15
    const int m0 = blockIdx.x * 64;
    const int n0 = blockIdx.y * 32;

    const int la_c = tid & 15;    // k within A tile
    const int la_r = tid >> 4;    // row base
    const int lb_n = tid & 31;    // n within W tile
    const int lb_c = tid >> 5;    // 0..7

    float acc[4][2];
#pragma unroll
    for (int i = 0; i < 4; i++) { acc[i][0] = 0.f; acc[i][1] = 0.f; }

    for (int k0 = 0; k0 < K; k0 += 16) {
#pragma unroll
        for (int qq = 0; qq < 4; qq++)
            As[la_c][la_r + 16*qq] = A[(size_t)(m0 + la_r + 16*qq) * K + k0 + la_c];
#pragma unroll
        for (int qq = 0; qq < 2; qq++)
            Bs[lb_c + 8*qq][lb_n] = W[(size_t)(k0 + lb_c + 8*qq) * N + n0 + lb_n];
        __syncthreads();
#pragma unroll
        for (int kk = 0; kk < 16; kk++) {
            float a0 = As[kk][ty*4+0], a1 = As[kk][ty*4+1];
            float a2 = As[kk][ty*4+2], a3 = As[kk][ty*4+3];
            float b0 = Bs[kk][tx*2+0], b1 = Bs[kk][tx*2+1];
            acc[0][0] += a0*b0; acc[0][1] += a0*b1;
            acc[1][0] += a1*b0; acc[1][1] += a1*b1;
            acc[2][0] += a2*b0; acc[2][1] += a2*b1;
            acc[3][0] += a3*b0; acc[3][1] += a3*b1;
        }
        __syncthreads();
    }
#pragma unroll
    for (int i = 0; i < 4; i++) {
#pragma unroll
        for (int jj = 0; jj < 2; jj++) {
            int m = m0 + ty*4 + i;
            int n = n0 + tx*2 + jj;
            float v = acc[i][jj];
            if (BIAS_RELU) { v += bias[n]; v = fmaxf(v, 0.f); }
            if (TRANS_OUT) {
                int bb = m >> 8;          // / 256
                int col = m & 255;
                C[(size_t)(bb*NH + n) * NS + col] = v;
            } else {
                C[(size_t)m * N + n] = v;
            }
        }
    }
}

// ---------------- fused attention + softmax + residual + LayerNorm ----------------
// grid = NROWS/8 = 128 blocks, 256 threads. 8 query rows per block.
__global__ void attn_ln_kernel(const float* __restrict__ Xin, const float* __restrict__ q,
                               const float* __restrict__ kT, const float* __restrict__ wv,
                               float* __restrict__ Xout) {
    const int G = 8;
    __shared__ float sq[G][NH];
    __shared__ float swv[NH];
    __shared__ float sp[G][NS];
    __shared__ float red1[G][8], red2[G][8];
    __shared__ float smean[G], srstd[G];

    const int tid = threadIdx.x;
    const int b  = blockIdx.x >> 5;          // / 32
    const int i0 = (blockIdx.x & 31) * G;
    const int wid = tid >> 5, lane = tid & 31;

    if (tid < NH) swv[tid] = wv[tid];
    for (int t = tid; t < G*NH; t += 256) {
        int r = t >> 7, h = t & 127;
        sq[r][h] = q[(size_t)(b*NS + i0 + r) * NH + h];
    }
    __syncthreads();

    // scores: thread owns key index j = tid
    {
        float sc[G];
#pragma unroll
        for (int r = 0; r < G; r++) sc[r] = 0.f;
        const float* kp = kT + (size_t)(b*NH) * NS + tid;
        for (int h = 0; h < NH; h++) {
            float kv = kp[(size_t)h * NS];
            float w  = swv[h];
#pragma unroll
            for (int r = 0; r < G; r++) sc[r] += w * tanhf(sq[r][h] + kv);
        }
#pragma unroll
        for (int r = 0; r < G; r++) sp[r][tid] = sc[r];
    }
    __syncthreads();

    // softmax: warp w owns row w
    {
        float mx = -1e30f;
        for (int jj = lane; jj < NS; jj += 32) mx = fmaxf(mx, sp[wid][jj]);
#pragma unroll
        for (int o = 16; o; o >>= 1) mx = fmaxf(mx, __shfl_xor_sync(0xffffffffu, mx, o));
        float sum = 0.f;
        for (int jj = lane; jj < NS; jj += 32) {
            float e = __expf(sp[wid][jj] - mx);
            sp[wid][jj] = e;
            sum += e;
        }
#pragma unroll
        for (int o = 16; o; o >>= 1) sum += __shfl_xor_sync(0xffffffffu, sum, o);
        float inv = 1.f / sum;
        for (int jj = lane; jj < NS; jj += 32) sp[wid][jj] *= inv;
    }
    __syncthreads();

    // A@V + residual; each thread owns columns d = tid + c*256 (c=0..4)
    float o[G][5];
#pragma unroll
    for (int r = 0; r < G; r++) {
        const float* xp = Xin + (size_t)(b*NS + i0 + r) * NV + tid;
#pragma unroll
        for (int c = 0; c < 5; c++) o[r][c] = xp[c*256];
    }
    for (int jj = 0; jj < NS; jj++) {
        const float* xp = Xin + (size_t)(b*NS + jj) * NV + tid;
        float x0 = xp[0], x1 = xp[256], x2 = xp[512], x3 = xp[768], x4 = xp[1024];
#pragma unroll
        for (int r = 0; r < G; r++) {
            float p = sp[r][jj];
            o[r][0] += p*x0; o[r][1] += p*x1; o[r][2] += p*x2;
            o[r][3] += p*x3; o[r][4] += p*x4;
        }
    }

    // LayerNorm per row
#pragma unroll
    for (int r = 0; r < G; r++) {
        float s1 = 0.f, s2 = 0.f;
#pragma unroll
        for (int c = 0; c < 5; c++) { s1 += o[r][c]; s2 += o[r][c]*o[r][c]; }
#pragma unroll
        for (int of = 16; of; of >>= 1) {
            s1 += __shfl_xor_sync(0xffffffffu, s1, of);
            s2 += __shfl_xor_sync(0xffffffffu, s2, of);
        }
        if (lane == 0) { red1[r][wid] = s1; red2[r][wid] = s2; }
    }
    __syncthreads();
    if (tid < G) {
        float s1 = 0.f, s2 = 0.f;
        for (int w = 0; w < 8; w++) { s1 += red1[tid][w]; s2 += red2[tid][w]; }
        float mean = s1 * (1.f / NV);
        float var  = s2 * (1.f / NV) - mean*mean;
        smean[tid] = mean;
        srstd[tid] = rsqrtf(var + EPSV);
    }
    __syncthreads();
#pragma unroll
    for (int r = 0; r < G; r++) {
        float mean = smean[r], rstd = srstd[r];
        float* op = Xout + (size_t)(b*NS + i0 + r) * NV + tid;
        op[0]    = (o[r][0]-mean)*rstd;
        op[256]  = (o[r][1]-mean)*rstd;
        op[512]  = (o[r][2]-mean)*rstd;
        op[768]  = (o[r][3]-mean)*rstd;
        op[1024] = (o[r][4]-mean)*rstd;
    }
}

// ---------------- fc2: out = h @ W2 + b2 + Xn ----------------
// grid = 128 blocks, 8 rows per block, 256 threads
__global__ void fc2_kernel(const float* __restrict__ h, const float* __restrict__ Xn,
                           const float* __restrict__ W2, const float* __restrict__ b2,
                           float* __restrict__ Xout) {
    const int G = 8;
    __shared__ float sh[G][NH];
    const int tid = threadIdx.x;
    const int row0 = blockIdx.x * G;

    for (int t = tid; t < G*NH; t += 256) {
        int r = t >> 7, k = t & 127;
        sh[r][k] = h[(size_t)(row0 + r) * NH + k];
    }
    __syncthreads();

    float bb[5];
#pragma unroll
    for (int c = 0; c < 5; c++) bb[c] = b2[tid + c*256];

    float o[G][5];
#pragma unroll
    for (int r = 0; r < G; r++) {
        const float* xp = Xn + (size_t)(row0 + r) * NV + tid;
#pragma unroll
        for (int c = 0; c < 5; c++) o[r][c] = bb[c] + xp[c*256];
    }
    for (int k = 0; k < NH; k++) {
        const float* wp = W2 + (size_t)k * NV + tid;
        float w0 = wp[0], w1 = wp[256], w2 = wp[512], w3 = wp[768], w4 = wp[1024];
#pragma unroll
        for (int r = 0; r < G; r++) {
            float hh = sh[r][k];
            o[r][0] += hh*w0; o[r][1] += hh*w1; o[r][2] += hh*w2;
            o[r][3] += hh*w3; o[r][4] += hh*w4;
        }
    }
#pragma unroll
    for (int r = 0; r < G; r++) {
        float* op = Xout + (size_t)(row0 + r) * NV + tid;
        op[0] = o[r][0]; op[256] = o[r][1]; op[512] = o[r][2];
        op[768] = o[r][3]; op[1024] = o[r][4];
    }
}

// ---------------- final: lys-row attention + LN + head MLP ----------------
// grid = 4 blocks (one per batch), 256 threads
__global__ void final_kernel(const float* __restrict__ X, const float* __restrict__ k4T,
                             const float* __restrict__ Wq4, const float* __restrict__ wv4,
                             const int* __restrict__ lys_pos,
                             const float* __restrict__ hW1, const float* __restrict__ hb1,
                             const float* __restrict__ hW2, const float* __restrict__ hb2,
                             const float* __restrict__ hW3, const float* __restrict__ hb3,
                             float* __restrict__ out) {
    __shared__ float xl[NV];
    __shared__ float q4[NH];
    __shared__ float sp[NS];
    __shared__ float swv[NH];
    __shared__ float red[32];
    __shared__ float h1s[32];
    __shared__ float h2s[12];
    __shared__ float stats[2];

    const int b = blockIdx.x, tid = threadIdx.x;
    const int wid = tid >> 5, lane = tid & 31;
    const int lp = *lys_pos;

    const float* xrow = X + (size_t)(b*NS + lp) * NV;
    for (int v = tid; v < NV; v += 256) xl[v] = xrow[v];
    if (tid < NH) swv[tid] = wv4[tid];
    __syncthreads();

    // q4 = xl @ Wq4
    if (tid < NH) {
        float s = 0.f;
        for (int v = 0; v < NV; v++) s += xl[v] * Wq4[(size_t)v * NH + tid];
        q4[tid] = s;
    }
    __syncthreads();

    // scores (one key j per thread)
    {
        float s = 0.f;
        const float* kp = k4T + (size_t)(b*NH) * NS + tid;
        for (int h = 0; h < NH; h++) s += swv[h] * tanhf(q4[h] + kp[(size_t)h * NS]);
        sp[tid] = s;
    }
    __syncthreads();

    // block softmax over 256
    float sv = sp[tid];
    float m = sv;
#pragma unroll
    for (int o = 16; o; o >>= 1) m = fmaxf(m, __shfl_xor_sync(0xffffffffu, m, o));
    if (lane == 0) red[wid] = m;
    __syncthreads();
    if (tid == 0) {
        float t = red[0];
        for (int w = 1; w < 8; w++) t = fmaxf(t, red[w]);
        red[8] = t;
    }
    __syncthreads();
    m = red[8];
    float e = __expf(sv - m);
    float ssum = e;
#pragma unroll
    for (int o = 16; o; o >>= 1) ssum += __shfl_xor_sync(0xffffffffu, ssum, o);
    if (lane == 0) red[16 + wid] = ssum;
    __syncthreads();
    if (tid == 0) {
        float t = 0.f;
        for (int w = 0; w < 8; w++) t += red[16 + w];
        red[24] = 1.f / t;
    }
    __syncthreads();
    float p = e * red[24];
    sp[tid] = p;
    __syncthreads();

    // ctx + residual
    float o5[5];
#pragma unroll
    for (int c = 0; c < 5; c++) o5[c] = xl[tid + c*256];
    for (int jj = 0; jj < NS; jj++) {
        const float* xp = X + (size_t)(b*NS + jj) * NV + tid;
        float pj = sp[jj];
        o5[0] += pj*xp[0]; o5[1] += pj*xp[256]; o5[2] += pj*xp[512];
        o5[3] += pj*xp[768]; o5[4] += pj*xp[1024];
    }

    // LayerNorm
    float s1 = 0.f, s2 = 0.f;
#pragma unroll
    for (int c = 0; c < 5; c++) { s1 += o5[c]; s2 += o5[c]*o5[c]; }
#pragma unroll
    for (int of = 16; of; of >>= 1) {
        s1 += __shfl_xor_sync(0xffffffffu, s1, of);
        s2 += __shfl_xor_sync(0xffffffffu, s2, of);
    }
    if (lane == 0) { red[wid] = s1; red[8 + wid] = s2; }
    __syncthreads();
    if (tid == 0) {
        float a = 0.f, bsq = 0.f;
        for (int w = 0; w < 8; w++) { a += red[w]; bsq += red[8 + w]; }
        float mean = a * (1.f / NV);
        float var  = bsq * (1.f / NV) - mean*mean;
        stats[0] = mean;
        stats[1] = rsqrtf(var + EPSV);
    }
    __syncthreads();
    {
        float mean = stats[0], rstd = stats[1];
#pragma unroll
        for (int c = 0; c < 5; c++) xl[tid + c*256] = (o5[c] - mean) * rstd;
    }
    __syncthreads();

    // head MLP: 1280 -> 32 -> 12 -> 2
    if (tid < 32) {
        float s = hb1[tid];
        for (int v = 0; v < NV; v++) s += xl[v] * hW1[(size_t)v * 32 + tid];
        h1s[tid] = fmaxf(s, 0.f);
    }
    __syncthreads();
    if (tid < 12) {
        float s = hb2[tid];
        for (int u = 0; u < 32; u++) s += h1s[u] * hW2[u*12 + tid];
        h2s[tid] = fmaxf(s, 0.f);
    }
    __syncthreads();
    if (tid < 2) {
        float s = hb3[tid];
        for (int u = 0; u < 12; u++) s += h2s[u] * hW3[u*2 + tid];
        out[b*2 + tid] = s;
    }
}

// ---------------- launch ----------------
extern "C" void kernel_launch(void* const* d_in, const int* in_sizes, int n_in,
                              void* d_out, int out_size) {
    const float* X   = (const float*)d_in[0];
    const int*   lys = (const int*)  d_in[1];
    const float* Wq[4]  = {(const float*)d_in[2],  (const float*)d_in[5],
                           (const float*)d_in[8],  (const float*)d_in[11]};
    const float* Wk[4]  = {(const float*)d_in[3],  (const float*)d_in[6],
                           (const float*)d_in[9],  (const float*)d_in[12]};
    const float* wv[4]  = {(const float*)d_in[4],  (const float*)d_in[7],
                           (const float*)d_in[10], (const float*)d_in[13]};
    const float* rW1[3] = {(const float*)d_in[14], (const float*)d_in[18], (const float*)d_in[22]};
    const float* rb1[3] = {(const float*)d_in[15], (const float*)d_in[19], (const float*)d_in[23]};
    const float* rW2[3] = {(const float*)d_in[16], (const float*)d_in[20], (const float*)d_in[24]};
    const float* rb2[3] = {(const float*)d_in[17], (const float*)d_in[21], (const float*)d_in[25]};
    const float* hW1 = (const float*)d_in[26];
    const float* hb1 = (const float*)d_in[27];
    const float* hW2 = (const float*)d_in[28];
    const float* hb2 = (const float*)d_in[29];
    const float* hW3 = (const float*)d_in[30];
    const float* hb3 = (const float*)d_in[31];
    float* out = (float*)d_out;

    float *q, *kT, *Xn, *h, *X2;
    cudaGetSymbolAddress((void**)&q,  g_q);
    cudaGetSymbolAddress((void**)&kT, g_kT);
    cudaGetSymbolAddress((void**)&Xn, g_Xn);
    cudaGetSymbolAddress((void**)&h,  g_h);
    cudaGetSymbolAddress((void**)&X2, g_X2);

    dim3 ggrid(NROWS/64, NH/32);   // (16, 4)
    const float* cur = X;
    for (int l = 0; l < 3; l++) {
        gemm_kernel<false, false><<<ggrid, 256>>>(cur, Wq[l], nullptr, q,  NROWS, NH, NV);
        gemm_kernel<false, true ><<<ggrid, 256>>>(cur, Wk[l], nullptr, kT, NROWS, NH, NV);
        attn_ln_kernel<<<NROWS/8, 256>>>(cur, q, kT, wv[l], Xn);
        gemm_kernel<true,  false><<<ggrid, 256>>>(Xn, rW1[l], rb1[l], h, NROWS, NH, NV);
        fc2_kernel<<<NROWS/8, 256>>>(h, Xn, rW2[l], rb2[l], X2);
        cur = X2;
    }
    gemm_kernel<false, true><<<ggrid, 256>>>(cur, Wk[3], nullptr, kT, NROWS, NH, NV);
    final_kernel<<<NB, 256>>>(cur, kT, Wq[3], wv[3], lys,
                              hW1, hb1, hW2, hb2, hW3, hb3, out);
}

// round 8
// speedup vs baseline: 1.6478x; 1.6478x over previous
#include <cuda_runtime.h>
#include <math.h>

#define NB 4
#define NS 256
#define NV 1280
#define NH 128
#define EPSV 1e-5f
#define NROWS (NB*NS)   // 1024
#define SPLITS 5
#define KCHUNK (NV/SPLITS)   // 256

// ---------------- scratch (no allocation allowed) ----------------
__device__ float g_q [NB*NS*NH];
__device__ float g_kT[NB*NH*NS];
__device__ float g_Xn[NB*NS*NV];
__device__ float g_h [NB*NS*NH];
__device__ float g_X2[NB*NS*NV];
__device__ float g_P [SPLITS * NROWS * 256];   // split-K partials (max N=256)

// fast tanh: 1 - 2/(e^{2x}+1); uses MUFU.EX2 + MUFU.RCP, rel err ~1e-6
__device__ __forceinline__ float fast_tanh(float x) {
    float e = __expf(2.0f * x);
    return 1.0f - __fdividef(2.0f, e + 1.0f);
}

// ---------------- split-K SGEMM: P[s] = A[:, sK:(s+1)K] @ W_chunk ----------------
// BM=64, BN=32, BK=16, 256 threads, 4x2 outputs per thread.
// Register-prefetch pipeline: next tile loads overlap current tile FMAs.
// NW=2: columns 0..127 from W0, 128..255 from W1 (fused q/k projection).
template<int NW>
__global__ void gemm_splitk(const float* __restrict__ A,
                            const float* __restrict__ W0,
                            const float* __restrict__ W1,
                            float* __restrict__ P) {
    __shared__ float As[16][65];
    __shared__ float Bs[16][32];
    const int tid = threadIdx.x;
    const int tx = tid & 15;      // 0..15
    const int ty = tid >> 4;      // 0..15
    const int m0 = blockIdx.x * 64;
    const int n0 = blockIdx.y * 32;
    const int s  = blockIdx.z;
    const int kbase = s * KCHUNK;
    const int N = NW * 128;

    const float* W = (NW == 2 && n0 >= 128) ? W1 : W0;
    const int nw0  = (NW == 2 && n0 >= 128) ? (n0 - 128) : n0;

    const int la_c = tid & 15;    // k within A tile
    const int la_r = tid >> 4;    // row base
    const int lb_n = tid & 31;    // n within W tile
    const int lb_c = tid >> 5;    // 0..7

    const float* Ap = A + (size_t)(m0 + la_r) * NV + kbase + la_c;
    const float* Wp = W + (size_t)(kbase + lb_c) * 128 + nw0 + lb_n;

    float ra[4], rb[2];
    // preload tile 0
#pragma unroll
    for (int qq = 0; qq < 4; qq++) ra[qq] = Ap[(size_t)(16*qq) * NV];
#pragma unroll
    for (int qq = 0; qq < 2; qq++) rb[qq] = Wp[(size_t)(8*qq) * 128];

    float acc[4][2];
#pragma unroll
    for (int i = 0; i < 4; i++) { acc[i][0] = 0.f; acc[i][1] = 0.f; }

    const int NTILES = KCHUNK / 16;   // 16
    for (int t = 0; t < NTILES; t++) {
        // store prefetched regs into smem
#pragma unroll
        for (int qq = 0; qq < 4; qq++) As[la_c][la_r + 16*qq] = ra[qq];
#pragma unroll
        for (int qq = 0; qq < 2; qq++) Bs[lb_c + 8*qq][lb_n] = rb[qq];
        __syncthreads();

        // prefetch next tile into regs (overlaps with FMAs below)
        if (t + 1 < NTILES) {
            const float* Ap2 = Ap + (t+1)*16;
            const float* Wp2 = Wp + (size_t)(t+1)*16 * 128;
#pragma unroll
            for (int qq = 0; qq < 4; qq++) ra[qq] = Ap2[(size_t)(16*qq) * NV];
#pragma unroll
            for (int qq = 0; qq < 2; qq++) rb[qq] = Wp2[(size_t)(8*qq) * 128];
        }

#pragma unroll
        for (int kk = 0; kk < 16; kk++) {
            float a0 = As[kk][ty*4+0], a1 = As[kk][ty*4+1];
            float a2 = As[kk][ty*4+2], a3 = As[kk][ty*4+3];
            float b0 = Bs[kk][tx*2+0], b1 = Bs[kk][tx*2+1];
            acc[0][0] += a0*b0; acc[0][1] += a0*b1;
            acc[1][0] += a1*b0; acc[1][1] += a1*b1;
            acc[2][0] += a2*b0; acc[2][1] += a2*b1;
            acc[3][0] += a3*b0; acc[3][1] += a3*b1;
        }
        __syncthreads();
    }
#pragma unroll
    for (int i = 0; i < 4; i++) {
#pragma unroll
        for (int jj = 0; jj < 2; jj++) {
            int m = m0 + ty*4 + i;
            int n = n0 + tx*2 + jj;
            P[((size_t)s * NROWS + m) * N + n] = acc[i][jj];
        }
    }
}

// ---- epilogue: sum splits; n<128 -> q (plain), n>=128 -> kT (transposed) ----
__global__ void epi_qk(const float* __restrict__ P, float* __restrict__ q,
                       float* __restrict__ kT) {
    int idx = blockIdx.x * 256 + threadIdx.x;   // over NROWS*256
    int m = idx >> 8, n = idx & 255;
    float v = 0.f;
#pragma unroll
    for (int s = 0; s < SPLITS; s++) v += P[((size_t)s * NROWS + m) * 256 + n];
    if (n < 128) {
        q[(size_t)m * NH + n] = v;
    } else {
        int b = m >> 8, col = m & 255;
        kT[((size_t)(b * NH + (n - 128))) * NS + col] = v;
    }
}

// ---- epilogue: sum splits + bias + relu (fc1) ----
__global__ void epi_bias_relu(const float* __restrict__ P, const float* __restrict__ bias,
                              float* __restrict__ outp) {
    int idx = blockIdx.x * 256 + threadIdx.x;   // over NROWS*128
    int m = idx >> 7, n = idx & 127;
    float v = bias[n];
#pragma unroll
    for (int s = 0; s < SPLITS; s++) v += P[((size_t)s * NROWS + m) * 128 + n];
    outp[idx] = fmaxf(v, 0.f);
}

// ---- epilogue: sum splits + transposed store (k4) ----
__global__ void epi_ktrans(const float* __restrict__ P, float* __restrict__ kT) {
    int idx = blockIdx.x * 256 + threadIdx.x;   // over NROWS*128
    int m = idx >> 7, n = idx & 127;
    float v = 0.f;
#pragma unroll
    for (int s = 0; s < SPLITS; s++) v += P[((size_t)s * NROWS + m) * 128 + n];
    int b = m >> 8, col = m & 255;
    kT[((size_t)(b * NH + n)) * NS + col] = v;
}

// ---------------- fused attention + softmax + residual + LayerNorm ----------------
// grid = NROWS/8 = 128 blocks, 256 threads. 8 query rows per block.
__global__ void attn_ln_kernel(const float* __restrict__ Xin, const float* __restrict__ q,
                               const float* __restrict__ kT, const float* __restrict__ wv,
                               float* __restrict__ Xout) {
    const int G = 8;
    __shared__ float sq[G][NH];
    __shared__ float swv[NH];
    __shared__ float sp[G][NS];
    __shared__ float red1[G][8], red2[G][8];
    __shared__ float smean[G], srstd[G];

    const int tid = threadIdx.x;
    const int b  = blockIdx.x >> 5;          // / 32
    const int i0 = (blockIdx.x & 31) * G;
    const int wid = tid >> 5, lane = tid & 31;

    if (tid < NH) swv[tid] = wv[tid];
    for (int t = tid; t < G*NH; t += 256) {
        int r = t >> 7, h = t & 127;
        sq[r][h] = q[(size_t)(b*NS + i0 + r) * NH + h];
    }
    __syncthreads();

    // scores: thread owns key index j = tid
    {
        float sc[G];
#pragma unroll
        for (int r = 0; r < G; r++) sc[r] = 0.f;
        const float* kp = kT + (size_t)(b*NH) * NS + tid;
        for (int h = 0; h < NH; h++) {
            float kv = kp[(size_t)h * NS];
            float w  = swv[h];
#pragma unroll
            for (int r = 0; r < G; r++) sc[r] += w * fast_tanh(sq[r][h] + kv);
        }
#pragma unroll
        for (int r = 0; r < G; r++) sp[r][tid] = sc[r];
    }
    __syncthreads();

    // softmax: warp w owns row w
    {
        float mx = -1e30f;
        for (int jj = lane; jj < NS; jj += 32) mx = fmaxf(mx, sp[wid][jj]);
#pragma unroll
        for (int o = 16; o; o >>= 1) mx = fmaxf(mx, __shfl_xor_sync(0xffffffffu, mx, o));
        float sum = 0.f;
        for (int jj = lane; jj < NS; jj += 32) {
            float e = __expf(sp[wid][jj] - mx);
            sp[wid][jj] = e;
            sum += e;
        }
#pragma unroll
        for (int o = 16; o; o >>= 1) sum += __shfl_xor_sync(0xffffffffu, sum, o);
        float inv = 1.f / sum;
        for (int jj = lane; jj < NS; jj += 32) sp[wid][jj] *= inv;
    }
    __syncthreads();

    // A@V + residual; each thread owns columns d = tid + c*256 (c=0..4)
    float o[G][5];
#pragma unroll
    for (int r = 0; r < G; r++) {
        const float* xp = Xin + (size_t)(b*NS + i0 + r) * NV + tid;
#pragma unroll
        for (int c = 0; c < 5; c++) o[r][c] = xp[c*256];
    }
    for (int jj = 0; jj < NS; jj++) {
        const float* xp = Xin + (size_t)(b*NS + jj) * NV + tid;
        float x0 = xp[0], x1 = xp[256], x2 = xp[512], x3 = xp[768], x4 = xp[1024];
#pragma unroll
        for (int r = 0; r < G; r++) {
            float p = sp[r][jj];
            o[r][0] += p*x0; o[r][1] += p*x1; o[r][2] += p*x2;
            o[r][3] += p*x3; o[r][4] += p*x4;
        }
    }

    // LayerNorm per row
#pragma unroll
    for (int r = 0; r < G; r++) {
        float s1 = 0.f, s2 = 0.f;
#pragma unroll
        for (int c = 0; c < 5; c++) { s1 += o[r][c]; s2 += o[r][c]*o[r][c]; }
#pragma unroll
        for (int of = 16; of; of >>= 1) {
            s1 += __shfl_xor_sync(0xffffffffu, s1, of);
            s2 += __shfl_xor_sync(0xffffffffu, s2, of);
        }
        if (lane == 0) { red1[r][wid] = s1; red2[r][wid] = s2; }
    }
    __syncthreads();
    if (tid < G) {
        float s1 = 0.f, s2 = 0.f;
        for (int w = 0; w < 8; w++) { s1 += red1[tid][w]; s2 += red2[tid][w]; }
        float mean = s1 * (1.f / NV);
        float var  = s2 * (1.f / NV) - mean*mean;
        smean[tid] = mean;
        srstd[tid] = rsqrtf(var + EPSV);
    }
    __syncthreads();
#pragma unroll
    for (int r = 0; r < G; r++) {
        float mean = smean[r], rstd = srstd[r];
        float* op = Xout + (size_t)(b*NS + i0 + r) * NV + tid;
        op[0]    = (o[r][0]-mean)*rstd;
        op[256]  = (o[r][1]-mean)*rstd;
        op[512]  = (o[r][2]-mean)*rstd;
        op[768]  = (o[r][3]-mean)*rstd;
        op[1024] = (o[r][4]-mean)*rstd;
    }
}

// ---------------- fc2: out = h @ W2 + b2 + Xn ----------------
// grid = 128 blocks, 8 rows per block, 256 threads
__global__ void fc2_kernel(const float* __restrict__ h, const float* __restrict__ Xn,
                           const float* __restrict__ W2, const float* __restrict__ b2,
                           float* __restrict__ Xout) {
    const int G = 8;
    __shared__ float sh[G][NH];
    const int tid = threadIdx.x;
    const int row0 = blockIdx.x * G;

    for (int t = tid; t < G*NH; t += 256) {
        int r = t >> 7, k = t & 127;
        sh[r][k] = h[(size_t)(row0 + r) * NH + k];
    }
    __syncthreads();

    float bb[5];
#pragma unroll
    for (int c = 0; c < 5; c++) bb[c] = b2[tid + c*256];

    float o[G][5];
#pragma unroll
    for (int r = 0; r < G; r++) {
        const float* xp = Xn + (size_t)(row0 + r) * NV + tid;
#pragma unroll
        for (int c = 0; c < 5; c++) o[r][c] = bb[c] + xp[c*256];
    }
    for (int k = 0; k < NH; k++) {
        const float* wp = W2 + (size_t)k * NV + tid;
        float w0 = wp[0], w1 = wp[256], w2 = wp[512], w3 = wp[768], w4 = wp[1024];
#pragma unroll
        for (int r = 0; r < G; r++) {
            float hh = sh[r][k];
            o[r][0] += hh*w0; o[r][1] += hh*w1; o[r][2] += hh*w2;
            o[r][3] += hh*w3; o[r][4] += hh*w4;
        }
    }
#pragma unroll
    for (int r = 0; r < G; r++) {
        float* op = Xout + (size_t)(row0 + r) * NV + tid;
        op[0] = o[r][0]; op[256] = o[r][1]; op[512] = o[r][2];
        op[768] = o[r][3]; op[1024] = o[r][4];
    }
}

// ---------------- final: lys-row attention + LN + head MLP ----------------
// grid = 4 blocks (one per batch), 256 threads
__global__ void final_kernel(const float* __restrict__ X, const float* __restrict__ k4T,
                             const float* __restrict__ Wq4, const float* __restrict__ wv4,
                             const int* __restrict__ lys_pos,
                             const float* __restrict__ hW1, const float* __restrict__ hb1,
                             const float* __restrict__ hW2, const float* __restrict__ hb2,
                             const float* __restrict__ hW3, const float* __restrict__ hb3,
                             float* __restrict__ out) {
    __shared__ float xl[NV];
    __shared__ float q4[NH];
    __shared__ float sp[NS];
    __shared__ float swv[NH];
    __shared__ float red[32];
    __shared__ float h1s[32];
    __shared__ float h2s[12];
    __shared__ float stats[2];

    const int b = blockIdx.x, tid = threadIdx.x;
    const int wid = tid >> 5, lane = tid & 31;
    const int lp = *lys_pos;

    const float* xrow = X + (size_t)(b*NS + lp) * NV;
    for (int v = tid; v < NV; v += 256) xl[v] = xrow[v];
    if (tid < NH) swv[tid] = wv4[tid];
    __syncthreads();

    // q4 = xl @ Wq4
    if (tid < NH) {
        float s = 0.f;
        for (int v = 0; v < NV; v++) s += xl[v] * Wq4[(size_t)v * NH + tid];
        q4[tid] = s;
    }
    __syncthreads();

    // scores (one key j per thread)
    {
        float s = 0.f;
        const float* kp = k4T + (size_t)(b*NH) * NS + tid;
        for (int h = 0; h < NH; h++) s += swv[h] * fast_tanh(q4[h] + kp[(size_t)h * NS]);
        sp[tid] = s;
    }
    __syncthreads();

    // block softmax over 256
    float sv = sp[tid];
    float m = sv;
#pragma unroll
    for (int o = 16; o; o >>= 1) m = fmaxf(m, __shfl_xor_sync(0xffffffffu, m, o));
    if (lane == 0) red[wid] = m;
    __syncthreads();
    if (tid == 0) {
        float t = red[0];
        for (int w = 1; w < 8; w++) t = fmaxf(t, red[w]);
        red[8] = t;
    }
    __syncthreads();
    m = red[8];
    float e = __expf(sv - m);
    float ssum = e;
#pragma unroll
    for (int o = 16; o; o >>= 1) ssum += __shfl_xor_sync(0xffffffffu, ssum, o);
    if (lane == 0) red[16 + wid] = ssum;
    __syncthreads();
    if (tid == 0) {
        float t = 0.f;
        for (int w = 0; w < 8; w++) t += red[16 + w];
        red[24] = 1.f / t;
    }
    __syncthreads();
    float p = e * red[24];
    sp[tid] = p;
    __syncthreads();

    // ctx + residual
    float o5[5];
#pragma unroll
    for (int c = 0; c < 5; c++) o5[c] = xl[tid + c*256];
    for (int jj = 0; jj < NS; jj++) {
        const float* xp = X + (size_t)(b*NS + jj) * NV + tid;
        float pj = sp[jj];
        o5[0] += pj*xp[0]; o5[1] += pj*xp[256]; o5[2] += pj*xp[512];
        o5[3] += pj*xp[768]; o5[4] += pj*xp[1024];
    }

    // LayerNorm
    float s1 = 0.f, s2 = 0.f;
#pragma unroll
    for (int c = 0; c < 5; c++) { s1 += o5[c]; s2 += o5[c]*o5[c]; }
#pragma unroll
    for (int of = 16; of; of >>= 1) {
        s1 += __shfl_xor_sync(0xffffffffu, s1, of);
        s2 += __shfl_xor_sync(0xffffffffu, s2, of);
    }
    if (lane == 0) { red[wid] = s1; red[8 + wid] = s2; }
    __syncthreads();
    if (tid == 0) {
        float a = 0.f, bsq = 0.f;
        for (int w = 0; w < 8; w++) { a += red[w]; bsq += red[8 + w]; }
        float mean = a * (1.f / NV);
        float var  = bsq * (1.f / NV) - mean*mean;
        stats[0] = mean;
        stats[1] = rsqrtf(var + EPSV);
    }
    __syncthreads();
    {
        float mean = stats[0], rstd = stats[1];
#pragma unroll
        for (int c = 0; c < 5; c++) xl[tid + c*256] = (o5[c] - mean) * rstd;
    }
    __syncthreads();

    // head MLP: 1280 -> 32 -> 12 -> 2
    if (tid < 32) {
        float s = hb1[tid];
        for (int v = 0; v < NV; v++) s += xl[v] * hW1[(size_t)v * 32 + tid];
        h1s[tid] = fmaxf(s, 0.f);
    }
    __syncthreads();
    if (tid < 12) {
        float s = hb2[tid];
        for (int u = 0; u < 32; u++) s += h1s[u] * hW2[u*12 + tid];
        h2s[tid] = fmaxf(s, 0.f);
    }
    __syncthreads();
    if (tid < 2) {
        float s = hb3[tid];
        for (int u = 0; u < 12; u++) s += h2s[u] * hW3[u*2 + tid];
        out[b*2 + tid] = s;
    }
}

// ---------------- launch ----------------
extern "C" void kernel_launch(void* const* d_in, const int* in_sizes, int n_in,
                              void* d_out, int out_size) {
    const float* X   = (const float*)d_in[0];
    const int*   lys = (const int*)  d_in[1];
    const float* Wq[4]  = {(const float*)d_in[2],  (const float*)d_in[5],
                           (const float*)d_in[8],  (const float*)d_in[11]};
    const float* Wk[4]  = {(const float*)d_in[3],  (const float*)d_in[6],
                           (const float*)d_in[9],  (const float*)d_in[12]};
    const float* wv[4]  = {(const float*)d_in[4],  (const float*)d_in[7],
                           (const float*)d_in[10], (const float*)d_in[13]};
    const float* rW1[3] = {(const float*)d_in[14], (const float*)d_in[18], (const float*)d_in[22]};
    const float* rb1[3] = {(const float*)d_in[15], (const float*)d_in[19], (const float*)d_in[23]};
    const float* rW2[3] = {(const float*)d_in[16], (const float*)d_in[20], (const float*)d_in[24]};
    const float* rb2[3] = {(const float*)d_in[17], (const float*)d_in[21], (const float*)d_in[25]};
    const float* hW1 = (const float*)d_in[26];
    const float* hb1 = (const float*)d_in[27];
    const float* hW2 = (const float*)d_in[28];
    const float* hb2 = (const float*)d_in[29];
    const float* hW3 = (const float*)d_in[30];
    const float* hb3 = (const float*)d_in[31];
    float* out = (float*)d_out;

    float *q, *kT, *Xn, *h, *X2, *P;
    cudaGetSymbolAddress((void**)&q,  g_q);
    cudaGetSymbolAddress((void**)&kT, g_kT);
    cudaGetSymbolAddress((void**)&Xn, g_Xn);
    cudaGetSymbolAddress((void**)&h,  g_h);
    cudaGetSymbolAddress((void**)&X2, g_X2);
    cudaGetSymbolAddress((void**)&P,  g_P);

    const float* cur = X;
    for (int l = 0; l < 3; l++) {
        // fused q+k projection: N=256, split-K over 5 chunks -> 640 blocks
        gemm_splitk<2><<<dim3(16, 8, SPLITS), 256>>>(cur, Wq[l], Wk[l], P);
        epi_qk<<<1024, 256>>>(P, q, kT);
        attn_ln_kernel<<<NROWS/8, 256>>>(cur, q, kT, wv[l], Xn);
        // fc1: N=128, split-K -> 320 blocks
        gemm_splitk<1><<<dim3(16, 4, SPLITS), 256>>>(Xn, rW1[l], nullptr, P);
        epi_bias_relu<<<512, 256>>>(P, rb1[l], h);
        fc2_kernel<<<NROWS/8, 256>>>(h, Xn, rW2[l], rb2[l], X2);
        cur = X2;
    }
    gemm_splitk<1><<<dim3(16, 4, SPLITS), 256>>>(cur, Wk[3], nullptr, P);
    epi_ktrans<<<512, 256>>>(P, kT);
    final_kernel<<<NB, 256>>>(cur, kT, Wq[3], wv[3], lys,
                              hW1, hb1, hW2, hb2, hW3, hb3, out);
}

// round 9
// speedup vs baseline: 2.0019x; 1.2149x over previous
#include <cuda_runtime.h>
#include <math.h>

#define NB 4
#define NS 256
#define NV 1280
#define NH 128
#define EPSV 1e-5f
#define NROWS (NB*NS)        // 1024
#define SPLITS 8
#define KCHUNK (NV/SPLITS)   // 160

// ---------------- scratch (no allocation allowed) ----------------
__device__ float g_q [NB*NS*NH];
__device__ float g_kT[NB*NH*NS];
__device__ float g_Xn[NB*NS*NV];
__device__ float g_h [NB*NS*NH];
__device__ float g_X2[NB*NS*NV];
__device__ float g_P [SPLITS * NROWS * 256];   // split-K partials (max N=256)

// single-MUFU tanh (MUFU.TANH), abs err ~1e-4 -- final rel_err budget is 1e-3
__device__ __forceinline__ float tanh_fast(float x) {
    float y;
    asm("tanh.approx.f32 %0, %1;" : "=f"(y) : "f"(x));
    return y;
}

// ---------------- split-K SGEMM: P[s] = A[:, sK:(s+1)K] @ W_chunk ----------------
// BM=64, BN=64, BK=16, 256 threads, 4x4 outputs/thread, float4 smem reads.
// Register-prefetch pipeline. NW=2: cols 0..127 from W0, 128..255 from W1.
template<int NW>
__global__ void gemm_splitk(const float* __restrict__ A,
                            const float* __restrict__ W0,
                            const float* __restrict__ W1,
                            float* __restrict__ P) {
    __shared__ __align__(16) float As[16][68];   // k-major, 272B stride (16B mult)
    __shared__ __align__(16) float Bs[16][64];
    const int tid = threadIdx.x;
    const int tx = tid & 15;          // n group (x4)
    const int ty = tid >> 4;          // m group (x4)
    const int m0 = blockIdx.x * 64;
    const int n0 = blockIdx.y * 64;
    const int s  = blockIdx.z;
    const int kbase = s * KCHUNK;
    const int N = NW * 128;

    const float* W = (NW == 2 && n0 >= 128) ? W1 : W0;
    const int nw0  = (NW == 2) ? (n0 & 127) : n0;

    // A loader: thread -> (row a_m, float4 k-chunk a_kc)
    const int a_kc = tid & 3;         // k = a_kc*4 .. +3
    const int a_m  = tid >> 2;        // 0..63
    // B loader: thread -> (k row b_r, float4 n col b_c)
    const int b_c = tid & 15;
    const int b_r = tid >> 4;

    const float* Ap = A + (size_t)(m0 + a_m) * NV + kbase + a_kc * 4;
    const float* Wp = W + (size_t)(kbase + b_r) * 128 + nw0 + b_c * 4;

    float4 ra = *(const float4*)Ap;
    float4 rb = *(const float4*)Wp;

    float acc[4][4] = {};

    const int NTILES = KCHUNK / 16;   // 10
    for (int t = 0; t < NTILES; t++) {
        // transpose-store A (4 scalar STS), vector-store B
        As[a_kc*4+0][a_m] = ra.x;
        As[a_kc*4+1][a_m] = ra.y;
        As[a_kc*4+2][a_m] = ra.z;
        As[a_kc*4+3][a_m] = ra.w;
        *(float4*)&Bs[b_r][b_c*4] = rb;
        __syncthreads();

        if (t + 1 < NTILES) {                       // prefetch next tile
            ra = *(const float4*)(Ap + (t+1)*16);
            rb = *(const float4*)(Wp + (size_t)(t+1)*16*128);
        }

#pragma unroll
        for (int kk = 0; kk < 16; kk++) {
            float4 av = *(const float4*)&As[kk][ty*4];
            float4 bv = *(const float4*)&Bs[kk][tx*4];
            acc[0][0] += av.x*bv.x; acc[0][1] += av.x*bv.y; acc[0][2] += av.x*bv.z; acc[0][3] += av.x*bv.w;
            acc[1][0] += av.y*bv.x; acc[1][1] += av.y*bv.y; acc[1][2] += av.y*bv.z; acc[1][3] += av.y*bv.w;
            acc[2][0] += av.z*bv.x; acc[2][1] += av.z*bv.y; acc[2][2] += av.z*bv.z; acc[2][3] += av.z*bv.w;
            acc[3][0] += av.w*bv.x; acc[3][1] += av.w*bv.y; acc[3][2] += av.w*bv.z; acc[3][3] += av.w*bv.w;
        }
        __syncthreads();
    }
#pragma unroll
    for (int i = 0; i < 4; i++) {
        float4 v = make_float4(acc[i][0], acc[i][1], acc[i][2], acc[i][3]);
        *(float4*)&P[((size_t)s * NROWS + m0 + ty*4 + i) * N + n0 + tx*4] = v;
    }
}

// ---- epilogue qk: sum splits; n<128 -> q, n>=128 -> kT (transposed) ----
__global__ void epi_qk(const float* __restrict__ P, float* __restrict__ q,
                       float* __restrict__ kT) {
    int gid = blockIdx.x * 256 + threadIdx.x;   // over NROWS*256/4 = 65536
    int m = gid >> 6, n = (gid & 63) * 4;
    float4 v = make_float4(0.f, 0.f, 0.f, 0.f);
#pragma unroll
    for (int s = 0; s < SPLITS; s++) {
        float4 p = *(const float4*)&P[((size_t)s * NROWS + m) * 256 + n];
        v.x += p.x; v.y += p.y; v.z += p.z; v.w += p.w;
    }
    if (n < 128) {
        *(float4*)&q[(size_t)m * NH + n] = v;
    } else {
        int b = m >> 8, col = m & 255;
        int h = n - 128;
        kT[((size_t)(b*NH + h+0)) * NS + col] = v.x;
        kT[((size_t)(b*NH + h+1)) * NS + col] = v.y;
        kT[((size_t)(b*NH + h+2)) * NS + col] = v.z;
        kT[((size_t)(b*NH + h+3)) * NS + col] = v.w;
    }
}

// ---- epilogue fc1: sum splits + bias + relu ----
__global__ void epi_bias_relu(const float* __restrict__ P, const float* __restrict__ bias,
                              float* __restrict__ outp) {
    int gid = blockIdx.x * 256 + threadIdx.x;   // over NROWS*128/4 = 32768
    int m = gid >> 5, n = (gid & 31) * 4;
    float4 v = *(const float4*)&bias[n];
#pragma unroll
    for (int s = 0; s < SPLITS; s++) {
        float4 p = *(const float4*)&P[((size_t)s * NROWS + m) * 128 + n];
        v.x += p.x; v.y += p.y; v.z += p.z; v.w += p.w;
    }
    v.x = fmaxf(v.x, 0.f); v.y = fmaxf(v.y, 0.f);
    v.z = fmaxf(v.z, 0.f); v.w = fmaxf(v.w, 0.f);
    *(float4*)&outp[(size_t)m * NH + n] = v;
}

// ---- epilogue k4: sum splits + transposed store ----
__global__ void epi_ktrans(const float* __restrict__ P, float* __restrict__ kT) {
    int gid = blockIdx.x * 256 + threadIdx.x;   // over NROWS*128/4
    int m = gid >> 5, n = (gid & 31) * 4;
    float4 v = make_float4(0.f, 0.f, 0.f, 0.f);
#pragma unroll
    for (int s = 0; s < SPLITS; s++) {
        float4 p = *(const float4*)&P[((size_t)s * NROWS + m) * 128 + n];
        v.x += p.x; v.y += p.y; v.z += p.z; v.w += p.w;
    }
    int b = m >> 8, col = m & 255;
    kT[((size_t)(b*NH + n+0)) * NS + col] = v.x;
    kT[((size_t)(b*NH + n+1)) * NS + col] = v.y;
    kT[((size_t)(b*NH + n+2)) * NS + col] = v.z;
    kT[((size_t)(b*NH + n+3)) * NS + col] = v.w;
}

// ---------------- fused attention + softmax + residual + LayerNorm ----------------
// grid = 128 blocks, 256 threads, 8 query rows/block.
// Column ownership: thread owns float4 at tid*4 plus scalar at 1024+tid.
__global__ void attn_ln_kernel(const float* __restrict__ Xin, const float* __restrict__ q,
                               const float* __restrict__ kT, const float* __restrict__ wv,
                               float* __restrict__ Xout) {
    const int G = 8;
    __shared__ float sq[G][NH];
    __shared__ float swv[NH];
    __shared__ float sp[G][NS];
    __shared__ float red1[G][8], red2[G][8];
    __shared__ float smean[G], srstd[G];

    const int tid = threadIdx.x;
    const int b  = blockIdx.x >> 5;
    const int i0 = (blockIdx.x & 31) * G;
    const int wid = tid >> 5, lane = tid & 31;

    if (tid < NH) swv[tid] = wv[tid];
    for (int t = tid; t < G*NH; t += 256) {
        int r = t >> 7, h = t & 127;
        sq[r][h] = q[(size_t)(b*NS + i0 + r) * NH + h];
    }
    __syncthreads();

    // scores: thread owns key index j = tid
    {
        float sc[G];
#pragma unroll
        for (int r = 0; r < G; r++) sc[r] = 0.f;
        const float* kp = kT + (size_t)(b*NH) * NS + tid;
        for (int h = 0; h < NH; h++) {
            float kv = kp[(size_t)h * NS];
            float w  = swv[h];
#pragma unroll
            for (int r = 0; r < G; r++) sc[r] += w * tanh_fast(sq[r][h] + kv);
        }
#pragma unroll
        for (int r = 0; r < G; r++) sp[r][tid] = sc[r];
    }
    __syncthreads();

    // softmax: warp w owns row w
    {
        float mx = -1e30f;
        for (int jj = lane; jj < NS; jj += 32) mx = fmaxf(mx, sp[wid][jj]);
#pragma unroll
        for (int o = 16; o; o >>= 1) mx = fmaxf(mx, __shfl_xor_sync(0xffffffffu, mx, o));
        float sum = 0.f;
        for (int jj = lane; jj < NS; jj += 32) {
            float e = __expf(sp[wid][jj] - mx);
            sp[wid][jj] = e;
            sum += e;
        }
#pragma unroll
        for (int o = 16; o; o >>= 1) sum += __shfl_xor_sync(0xffffffffu, sum, o);
        float inv = 1.f / sum;
        for (int jj = lane; jj < NS; jj += 32) sp[wid][jj] *= inv;
    }
    __syncthreads();

    // A@V + residual
    float4 o4[G]; float o1[G];
#pragma unroll
    for (int r = 0; r < G; r++) {
        const float* xp = Xin + (size_t)(b*NS + i0 + r) * NV;
        o4[r] = *(const float4*)(xp + tid*4);
        o1[r] = xp[1024 + tid];
    }
    for (int jj = 0; jj < NS; jj++) {
        const float* xp = Xin + (size_t)(b*NS + jj) * NV;
        float4 xv = *(const float4*)(xp + tid*4);
        float  xs = xp[1024 + tid];
#pragma unroll
        for (int r = 0; r < G; r++) {
            float p = sp[r][jj];
            o4[r].x += p*xv.x; o4[r].y += p*xv.y;
            o4[r].z += p*xv.z; o4[r].w += p*xv.w;
            o1[r]   += p*xs;
        }
    }

    // LayerNorm per row
#pragma unroll
    for (int r = 0; r < G; r++) {
        float s1 = o4[r].x + o4[r].y + o4[r].z + o4[r].w + o1[r];
        float s2 = o4[r].x*o4[r].x + o4[r].y*o4[r].y + o4[r].z*o4[r].z
                 + o4[r].w*o4[r].w + o1[r]*o1[r];
#pragma unroll
        for (int of = 16; of; of >>= 1) {
            s1 += __shfl_xor_sync(0xffffffffu, s1, of);
            s2 += __shfl_xor_sync(0xffffffffu, s2, of);
        }
        if (lane == 0) { red1[r][wid] = s1; red2[r][wid] = s2; }
    }
    __syncthreads();
    if (tid < G) {
        float s1 = 0.f, s2 = 0.f;
        for (int w = 0; w < 8; w++) { s1 += red1[tid][w]; s2 += red2[tid][w]; }
        float mean = s1 * (1.f / NV);
        float var  = s2 * (1.f / NV) - mean*mean;
        smean[tid] = mean;
        srstd[tid] = rsqrtf(var + EPSV);
    }
    __syncthreads();
#pragma unroll
    for (int r = 0; r < G; r++) {
        float mean = smean[r], rstd = srstd[r];
        float* op = Xout + (size_t)(b*NS + i0 + r) * NV;
        float4 v;
        v.x = (o4[r].x - mean) * rstd;
        v.y = (o4[r].y - mean) * rstd;
        v.z = (o4[r].z - mean) * rstd;
        v.w = (o4[r].w - mean) * rstd;
        *(float4*)(op + tid*4) = v;
        op[1024 + tid] = (o1[r] - mean) * rstd;
    }
}

// ---------------- fc2: out = h @ W2 + b2 + Xn ----------------
__global__ void fc2_kernel(const float* __restrict__ h, const float* __restrict__ Xn,
                           const float* __restrict__ W2, const float* __restrict__ b2,
                           float* __restrict__ Xout) {
    const int G = 8;
    __shared__ float sh[G][NH];
    const int tid = threadIdx.x;
    const int row0 = blockIdx.x * G;

    for (int t = tid; t < G*NH; t += 256) {
        int r = t >> 7, k = t & 127;
        sh[r][k] = h[(size_t)(row0 + r) * NH + k];
    }
    __syncthreads();

    float4 bb4 = *(const float4*)(b2 + tid*4);
    float  bb1 = b2[1024 + tid];

    float4 o4[G]; float o1[G];
#pragma unroll
    for (int r = 0; r < G; r++) {
        const float* xp = Xn + (size_t)(row0 + r) * NV;
        float4 xv = *(const float4*)(xp + tid*4);
        o4[r].x = bb4.x + xv.x; o4[r].y = bb4.y + xv.y;
        o4[r].z = bb4.z + xv.z; o4[r].w = bb4.w + xv.w;
        o1[r]   = bb1 + xp[1024 + tid];
    }
    for (int k = 0; k < NH; k++) {
        const float* wp = W2 + (size_t)k * NV;
        float4 wv4 = *(const float4*)(wp + tid*4);
        float  ws  = wp[1024 + tid];
#pragma unroll
        for (int r = 0; r < G; r++) {
            float hh = sh[r][k];
            o4[r].x += hh*wv4.x; o4[r].y += hh*wv4.y;
            o4[r].z += hh*wv4.z; o4[r].w += hh*wv4.w;
            o1[r]   += hh*ws;
        }
    }
#pragma unroll
    for (int r = 0; r < G; r++) {
        float* op = Xout + (size_t)(row0 + r) * NV;
        *(float4*)(op + tid*4) = o4[r];
        op[1024 + tid] = o1[r];
    }
}

// ---------------- final: lys-row attention + LN + head MLP ----------------
__global__ void final_kernel(const float* __restrict__ X, const float* __restrict__ k4T,
                             const float* __restrict__ Wq4, const float* __restrict__ wv4,
                             const int* __restrict__ lys_pos,
                             const float* __restrict__ hW1, const float* __restrict__ hb1,
                             const float* __restrict__ hW2, const float* __restrict__ hb2,
                             const float* __restrict__ hW3, const float* __restrict__ hb3,
                             float* __restrict__ out) {
    __shared__ float xl[NV];
    __shared__ float q4[NH];
    __shared__ float sp[NS];
    __shared__ float swv[NH];
    __shared__ float red[32];
    __shared__ float h1s[32];
    __shared__ float h2s[12];
    __shared__ float stats[2];

    const int b = blockIdx.x, tid = threadIdx.x;
    const int wid = tid >> 5, lane = tid & 31;
    const int lp = *lys_pos;

    const float* xrow = X + (size_t)(b*NS + lp) * NV;
    for (int v = tid; v < NV; v += 256) xl[v] = xrow[v];
    if (tid < NH) swv[tid] = wv4[tid];
    __syncthreads();

    if (tid < NH) {
        float s = 0.f;
        for (int v = 0; v < NV; v++) s += xl[v] * Wq4[(size_t)v * NH + tid];
        q4[tid] = s;
    }
    __syncthreads();

    {
        float s = 0.f;
        const float* kp = k4T + (size_t)(b*NH) * NS + tid;
        for (int h = 0; h < NH; h++) s += swv[h] * tanh_fast(q4[h] + kp[(size_t)h * NS]);
        sp[tid] = s;
    }
    __syncthreads();

    float sv = sp[tid];
    float m = sv;
#pragma unroll
    for (int o = 16; o; o >>= 1) m = fmaxf(m, __shfl_xor_sync(0xffffffffu, m, o));
    if (lane == 0) red[wid] = m;
    __syncthreads();
    if (tid == 0) {
        float t = red[0];
        for (int w = 1; w < 8; w++) t = fmaxf(t, red[w]);
        red[8] = t;
    }
    __syncthreads();
    m = red[8];
    float e = __expf(sv - m);
    float ssum = e;
#pragma unroll
    for (int o = 16; o; o >>= 1) ssum += __shfl_xor_sync(0xffffffffu, ssum, o);
    if (lane == 0) red[16 + wid] = ssum;
    __syncthreads();
    if (tid == 0) {
        float t = 0.f;
        for (int w = 0; w < 8; w++) t += red[16 + w];
        red[24] = 1.f / t;
    }
    __syncthreads();
    sp[tid] = e * red[24];
    __syncthreads();

    float4 o4 = *(const float4*)(xl + 0) ; // placeholder, re-set below
    // ctx + residual (float4 + scalar column ownership)
    {
        o4 = make_float4(xl[tid*4], xl[tid*4+1], xl[tid*4+2], xl[tid*4+3]);
    }
    float o1 = xl[1024 + tid];
    for (int jj = 0; jj < NS; jj++) {
        const float* xp = X + (size_t)(b*NS + jj) * NV;
        float4 xv = *(const float4*)(xp + tid*4);
        float pj = sp[jj];
        o4.x += pj*xv.x; o4.y += pj*xv.y; o4.z += pj*xv.z; o4.w += pj*xv.w;
        o1 += pj*xp[1024 + tid];
    }

    float s1 = o4.x + o4.y + o4.z + o4.w + o1;
    float s2 = o4.x*o4.x + o4.y*o4.y + o4.z*o4.z + o4.w*o4.w + o1*o1;
#pragma unroll
    for (int of = 16; of; of >>= 1) {
        s1 += __shfl_xor_sync(0xffffffffu, s1, of);
        s2 += __shfl_xor_sync(0xffffffffu, s2, of);
    }
    if (lane == 0) { red[wid] = s1; red[8 + wid] = s2; }
    __syncthreads();
    if (tid == 0) {
        float a = 0.f, bsq = 0.f;
        for (int w = 0; w < 8; w++) { a += red[w]; bsq += red[8 + w]; }
        float mean = a * (1.f / NV);
        float var  = bsq * (1.f / NV) - mean*mean;
        stats[0] = mean;
        stats[1] = rsqrtf(var + EPSV);
    }
    __syncthreads();
    {
        float mean = stats[0], rstd = stats[1];
        xl[tid*4+0] = (o4.x - mean) * rstd;
        xl[tid*4+1] = (o4.y - mean) * rstd;
        xl[tid*4+2] = (o4.z - mean) * rstd;
        xl[tid*4+3] = (o4.w - mean) * rstd;
        xl[1024 + tid] = (o1 - mean) * rstd;
    }
    __syncthreads();

    // head MLP: 1280 -> 32 -> 12 -> 2
    if (tid < 32) {
        float s = hb1[tid];
        for (int v = 0; v < NV; v++) s += xl[v] * hW1[(size_t)v * 32 + tid];
        h1s[tid] = fmaxf(s, 0.f);
    }
    __syncthreads();
    if (tid < 12) {
        float s = hb2[tid];
        for (int u = 0; u < 32; u++) s += h1s[u] * hW2[u*12 + tid];
        h2s[tid] = fmaxf(s, 0.f);
    }
    __syncthreads();
    if (tid < 2) {
        float s = hb3[tid];
        for (int u = 0; u < 12; u++) s += h2s[u] * hW3[u*2 + tid];
        out[b*2 + tid] = s;
    }
}

// ---------------- launch ----------------
extern "C" void kernel_launch(void* const* d_in, const int* in_sizes, int n_in,
                              void* d_out, int out_size) {
    const float* X   = (const float*)d_in[0];
    const int*   lys = (const int*)  d_in[1];
    const float* Wq[4]  = {(const float*)d_in[2],  (const float*)d_in[5],
                           (const float*)d_in[8],  (const float*)d_in[11]};
    const float* Wk[4]  = {(const float*)d_in[3],  (const float*)d_in[6],
                           (const float*)d_in[9],  (const float*)d_in[12]};
    const float* wv[4]  = {(const float*)d_in[4],  (const float*)d_in[7],
                           (const float*)d_in[10], (const float*)d_in[13]};
    const float* rW1[3] = {(const float*)d_in[14], (const float*)d_in[18], (const float*)d_in[22]};
    const float* rb1[3] = {(const float*)d_in[15], (const float*)d_in[19], (const float*)d_in[23]};
    const float* rW2[3] = {(const float*)d_in[16], (const float*)d_in[20], (const float*)d_in[24]};
    const float* rb2[3] = {(const float*)d_in[17], (const float*)d_in[21], (const float*)d_in[25]};
    const float* hW1 = (const float*)d_in[26];
    const float* hb1 = (const float*)d_in[27];
    const float* hW2 = (const float*)d_in[28];
    const float* hb2 = (const float*)d_in[29];
    const float* hW3 = (const float*)d_in[30];
    const float* hb3 = (const float*)d_in[31];
    float* out = (float*)d_out;

    float *q, *kT, *Xn, *h, *X2, *P;
    cudaGetSymbolAddress((void**)&q,  g_q);
    cudaGetSymbolAddress((void**)&kT, g_kT);
    cudaGetSymbolAddress((void**)&Xn, g_Xn);
    cudaGetSymbolAddress((void**)&h,  g_h);
    cudaGetSymbolAddress((void**)&X2, g_X2);
    cudaGetSymbolAddress((void**)&P,  g_P);

    const float* cur = X;
    for (int l = 0; l < 3; l++) {
        // fused q+k projection: N=256 -> grid (16,4,8) = 512 blocks
        gemm_splitk<2><<<dim3(16, 4, SPLITS), 256>>>(cur, Wq[l], Wk[l], P);
        epi_qk<<<256, 256>>>(P, q, kT);
        attn_ln_kernel<<<NROWS/8, 256>>>(cur, q, kT, wv[l], Xn);
        // fc1: N=128 -> grid (16,2,8) = 256 blocks
        gemm_splitk<1><<<dim3(16, 2, SPLITS), 256>>>(Xn, rW1[l], nullptr, P);
        epi_bias_relu<<<128, 256>>>(P, rb1[l], h);
        fc2_kernel<<<NROWS/8, 256>>>(h, Xn, rW2[l], rb2[l], X2);
        cur = X2;
    }
    gemm_splitk<1><<<dim3(16, 2, SPLITS), 256>>>(cur, Wk[3], nullptr, P);
    epi_ktrans<<<128, 256>>>(P, kT);
    final_kernel<<<NB, 256>>>(cur, kT, Wq[3], wv[3], lys,
                              hW1, hb1, hW2, hb2, hW3, hb3, out);
}

// round 11
// speedup vs baseline: 2.2714x; 1.1346x over previous
#include <cuda_runtime.h>
#include <math.h>

#define NB 4
#define NS 256
#define NV 1280
#define NH 128
#define EPSV 1e-5f
#define NROWS (NB*NS)        // 1024
#define SPLITS 8
#define KCHUNK (NV/SPLITS)   // 160

// ---------------- scratch (no allocation allowed) ----------------
__device__ float g_q [NB*NS*NH];
__device__ float g_kT[NB*NH*NS];
__device__ float g_Xn[NB*NS*NV];
__device__ float g_h [NB*NS*NH];
__device__ float g_X2[NB*NS*NV];
__device__ float g_Y [NB*NS*NV];               // pre-LN attention output
__device__ float g_S [NB*NS*NS];               // softmax probabilities
__device__ float g_P [SPLITS * NROWS * 256];   // split-K partials (max N=256)

// single-MUFU tanh (MUFU.TANH)
__device__ __forceinline__ float tanh_fast(float x) {
    float y;
    asm("tanh.approx.f32 %0, %1;" : "=f"(y) : "f"(x));
    return y;
}

// ---------------- split-K SGEMM: P[s] = A[:, sK:(s+1)K] @ W_chunk ----------------
// BM=64, BN=64, BK=16, 256 threads, 4x4 outputs/thread, float4 smem reads.
template<int NW>
__global__ void gemm_splitk(const float* __restrict__ A,
                            const float* __restrict__ W0,
                            const float* __restrict__ W1,
                            float* __restrict__ P) {
    __shared__ __align__(16) float As[16][68];
    __shared__ __align__(16) float Bs[16][64];
    const int tid = threadIdx.x;
    const int tx = tid & 15;
    const int ty = tid >> 4;
    const int m0 = blockIdx.x * 64;
    const int n0 = blockIdx.y * 64;
    const int s  = blockIdx.z;
    const int kbase = s * KCHUNK;
    const int N = NW * 128;

    const float* W = (NW == 2 && n0 >= 128) ? W1 : W0;
    const int nw0  = (NW == 2) ? (n0 & 127) : n0;

    const int a_kc = tid & 3;
    const int a_m  = tid >> 2;
    const int b_c = tid & 15;
    const int b_r = tid >> 4;

    const float* Ap = A + (size_t)(m0 + a_m) * NV + kbase + a_kc * 4;
    const float* Wp = W + (size_t)(kbase + b_r) * 128 + nw0 + b_c * 4;

    float4 ra = *(const float4*)Ap;
    float4 rb = *(const float4*)Wp;

    float acc[4][4] = {};

    const int NTILES = KCHUNK / 16;   // 10
    for (int t = 0; t < NTILES; t++) {
        As[a_kc*4+0][a_m] = ra.x;
        As[a_kc*4+1][a_m] = ra.y;
        As[a_kc*4+2][a_m] = ra.z;
        As[a_kc*4+3][a_m] = ra.w;
        *(float4*)&Bs[b_r][b_c*4] = rb;
        __syncthreads();

        if (t + 1 < NTILES) {
            ra = *(const float4*)(Ap + (t+1)*16);
            rb = *(const float4*)(Wp + (size_t)(t+1)*16*128);
        }

#pragma unroll
        for (int kk = 0; kk < 16; kk++) {
            float4 av = *(const float4*)&As[kk][ty*4];
            float4 bv = *(const float4*)&Bs[kk][tx*4];
            acc[0][0] += av.x*bv.x; acc[0][1] += av.x*bv.y; acc[0][2] += av.x*bv.z; acc[0][3] += av.x*bv.w;
            acc[1][0] += av.y*bv.x; acc[1][1] += av.y*bv.y; acc[1][2] += av.y*bv.z; acc[1][3] += av.y*bv.w;
            acc[2][0] += av.z*bv.x; acc[2][1] += av.z*bv.y; acc[2][2] += av.z*bv.z; acc[2][3] += av.z*bv.w;
            acc[3][0] += av.w*bv.x; acc[3][1] += av.w*bv.y; acc[3][2] += av.w*bv.z; acc[3][3] += av.w*bv.w;
        }
        __syncthreads();
    }
#pragma unroll
    for (int i = 0; i < 4; i++) {
        float4 v = make_float4(acc[i][0], acc[i][1], acc[i][2], acc[i][3]);
        *(float4*)&P[((size_t)s * NROWS + m0 + ty*4 + i) * N + n0 + tx*4] = v;
    }
}

// ---- epilogue qk: sum splits; n<128 -> q, n>=128 -> kT (transposed) ----
__global__ void epi_qk(const float* __restrict__ P, float* __restrict__ q,
                       float* __restrict__ kT) {
    int gid = blockIdx.x * 256 + threadIdx.x;
    int m = gid >> 6, n = (gid & 63) * 4;
    float4 v = make_float4(0.f, 0.f, 0.f, 0.f);
#pragma unroll
    for (int s = 0; s < SPLITS; s++) {
        float4 p = *(const float4*)&P[((size_t)s * NROWS + m) * 256 + n];
        v.x += p.x; v.y += p.y; v.z += p.z; v.w += p.w;
    }
    if (n < 128) {
        *(float4*)&q[(size_t)m * NH + n] = v;
    } else {
        int b = m >> 8, col = m & 255;
        int h = n - 128;
        kT[((size_t)(b*NH + h+0)) * NS + col] = v.x;
        kT[((size_t)(b*NH + h+1)) * NS + col] = v.y;
        kT[((size_t)(b*NH + h+2)) * NS + col] = v.z;
        kT[((size_t)(b*NH + h+3)) * NS + col] = v.w;
    }
}

// ---- epilogue fc1: sum splits + bias + relu ----
__global__ void epi_bias_relu(const float* __restrict__ P, const float* __restrict__ bias,
                              float* __restrict__ outp) {
    int gid = blockIdx.x * 256 + threadIdx.x;
    int m = gid >> 5, n = (gid & 31) * 4;
    float4 v = *(const float4*)&bias[n];
#pragma unroll
    for (int s = 0; s < SPLITS; s++) {
        float4 p = *(const float4*)&P[((size_t)s * NROWS + m) * 128 + n];
        v.x += p.x; v.y += p.y; v.z += p.z; v.w += p.w;
    }
    v.x = fmaxf(v.x, 0.f); v.y = fmaxf(v.y, 0.f);
    v.z = fmaxf(v.z, 0.f); v.w = fmaxf(v.w, 0.f);
    *(float4*)&outp[(size_t)m * NH + n] = v;
}

// ---- epilogue k4: sum splits + transposed store ----
__global__ void epi_ktrans(const float* __restrict__ P, float* __restrict__ kT) {
    int gid = blockIdx.x * 256 + threadIdx.x;
    int m = gid >> 5, n = (gid & 31) * 4;
    float4 v = make_float4(0.f, 0.f, 0.f, 0.f);
#pragma unroll
    for (int s = 0; s < SPLITS; s++) {
        float4 p = *(const float4*)&P[((size_t)s * NROWS + m) * 128 + n];
        v.x += p.x; v.y += p.y; v.z += p.z; v.w += p.w;
    }
    int b = m >> 8, col = m & 255;
    kT[((size_t)(b*NH + n+0)) * NS + col] = v.x;
    kT[((size_t)(b*NH + n+1)) * NS + col] = v.y;
    kT[((size_t)(b*NH + n+2)) * NS + col] = v.z;
    kT[((size_t)(b*NH + n+3)) * NS + col] = v.w;
}

// ---------------- scores + softmax -> S[b,i,j] ----------------
// grid = 128 blocks, 256 threads, 8 query rows/block.
__global__ void score_softmax(const float* __restrict__ q, const float* __restrict__ kT,
                              const float* __restrict__ wv, float* __restrict__ S) {
    const int G = 8;
    __shared__ float sq[G][NH];
    __shared__ float swv[NH];
    __shared__ float sp[G][NS];

    const int tid = threadIdx.x;
    const int b  = blockIdx.x >> 5;
    const int i0 = (blockIdx.x & 31) * G;
    const int wid = tid >> 5, lane = tid & 31;

    if (tid < NH) swv[tid] = wv[tid];
    for (int t = tid; t < G*NH; t += 256) {
        int r = t >> 7, h = t & 127;
        sq[r][h] = q[(size_t)(b*NS + i0 + r) * NH + h];
    }
    __syncthreads();

    // thread owns key index j = tid
    {
        float sc[G];
#pragma unroll
        for (int r = 0; r < G; r++) sc[r] = 0.f;
        const float* kp = kT + (size_t)(b*NH) * NS + tid;
        for (int h = 0; h < NH; h++) {
            float kv = kp[(size_t)h * NS];
            float w  = swv[h];
#pragma unroll
            for (int r = 0; r < G; r++) sc[r] += w * tanh_fast(sq[r][h] + kv);
        }
#pragma unroll
        for (int r = 0; r < G; r++) sp[r][tid] = sc[r];
    }
    __syncthreads();

    // softmax: warp w owns row w; write to S
    {
        float mx = -1e30f;
        for (int jj = lane; jj < NS; jj += 32) mx = fmaxf(mx, sp[wid][jj]);
#pragma unroll
        for (int o = 16; o; o >>= 1) mx = fmaxf(mx, __shfl_xor_sync(0xffffffffu, mx, o));
        float sum = 0.f;
        for (int jj = lane; jj < NS; jj += 32) {
            float e = __expf(sp[wid][jj] - mx);
            sp[wid][jj] = e;
            sum += e;
        }
#pragma unroll
        for (int o = 16; o; o >>= 1) sum += __shfl_xor_sync(0xffffffffu, sum, o);
        float inv = 1.f / sum;
        float* Sp = S + ((size_t)b*NS + i0 + wid) * NS;
        for (int jj = lane; jj < NS; jj += 32) Sp[jj] = sp[wid][jj] * inv;
    }
}

// ---------------- av_gemm: Y[b] = S[b] @ X[b] + X[b] ----------------
// per batch: M=256, N=1280, K=256. grid (4, 20, 4), BM=BN=64, BK=16.
__global__ void av_gemm(const float* __restrict__ S, const float* __restrict__ X,
                        float* __restrict__ Y) {
    __shared__ __align__(16) float As[16][68];
    __shared__ __align__(16) float Bs[16][64];
    const int tid = threadIdx.x;
    const int tx = tid & 15;
    const int ty = tid >> 4;
    const int m0 = blockIdx.x * 64;
    const int n0 = blockIdx.y * 64;
    const int b  = blockIdx.z;

    const float* A = S + (size_t)b * NS * NS;
    const float* B = X + (size_t)b * NS * NV;

    const int a_kc = tid & 3;
    const int a_m  = tid >> 2;
    const int b_c = tid & 15;
    const int b_r = tid >> 4;

    const float* Ap = A + (size_t)(m0 + a_m) * NS + a_kc * 4;
    const float* Bp = B + (size_t)b_r * NV + n0 + b_c * 4;

    float4 ra = *(const float4*)Ap;
    float4 rb = *(const float4*)Bp;

    float acc[4][4] = {};

    const int NTILES = NS / 16;   // 16
    for (int t = 0; t < NTILES; t++) {
        As[a_kc*4+0][a_m] = ra.x;
        As[a_kc*4+1][a_m] = ra.y;
        As[a_kc*4+2][a_m] = ra.z;
        As[a_kc*4+3][a_m] = ra.w;
        *(float4*)&Bs[b_r][b_c*4] = rb;
        __syncthreads();

        if (t + 1 < NTILES) {
            ra = *(const float4*)(Ap + (t+1)*16);
            rb = *(const float4*)(Bp + (size_t)(t+1)*16*NV);
        }

#pragma unroll
        for (int kk = 0; kk < 16; kk++) {
            float4 av = *(const float4*)&As[kk][ty*4];
            float4 bv = *(const float4*)&Bs[kk][tx*4];
            acc[0][0] += av.x*bv.x; acc[0][1] += av.x*bv.y; acc[0][2] += av.x*bv.z; acc[0][3] += av.x*bv.w;
            acc[1][0] += av.y*bv.x; acc[1][1] += av.y*bv.y; acc[1][2] += av.y*bv.z; acc[1][3] += av.y*bv.w;
            acc[2][0] += av.z*bv.x; acc[2][1] += av.z*bv.y; acc[2][2] += av.z*bv.z; acc[2][3] += av.z*bv.w;
            acc[3][0] += av.w*bv.x; acc[3][1] += av.w*bv.y; acc[3][2] += av.w*bv.z; acc[3][3] += av.w*bv.w;
        }
        __syncthreads();
    }
#pragma unroll
    for (int i = 0; i < 4; i++) {
        int row = m0 + ty*4 + i;
        const float4 xr = *(const float4*)&B[(size_t)row * NV + n0 + tx*4];
        float4 v = make_float4(acc[i][0] + xr.x, acc[i][1] + xr.y,
                               acc[i][2] + xr.z, acc[i][3] + xr.w);
        *(float4*)&Y[((size_t)b*NS + row) * NV + n0 + tx*4] = v;
    }
}

// ---------------- row LayerNorm: Xn = LN(Y), one warp per row ----------------
__global__ void ln_rows(const float* __restrict__ Y, float* __restrict__ Xn) {
    const int tid = threadIdx.x;
    const int wid = tid >> 5, lane = tid & 31;
    const int row = blockIdx.x * 8 + wid;

    const float* yp = Y + (size_t)row * NV;
    float4 v[10];
    float s1 = 0.f, s2 = 0.f;
#pragma unroll
    for (int w = 0; w < 10; w++) {
        v[w] = *(const float4*)(yp + w*128 + lane*4);
        s1 += v[w].x + v[w].y + v[w].z + v[w].w;
        s2 += v[w].x*v[w].x + v[w].y*v[w].y + v[w].z*v[w].z + v[w].w*v[w].w;
    }
#pragma unroll
    for (int o = 16; o; o >>= 1) {
        s1 += __shfl_xor_sync(0xffffffffu, s1, o);
        s2 += __shfl_xor_sync(0xffffffffu, s2, o);
    }
    float mean = s1 * (1.f / NV);
    float var  = s2 * (1.f / NV) - mean*mean;
    float rstd = rsqrtf(var + EPSV);

    float* op = Xn + (size_t)row * NV;
#pragma unroll
    for (int w = 0; w < 10; w++) {
        float4 r;
        r.x = (v[w].x - mean) * rstd;
        r.y = (v[w].y - mean) * rstd;
        r.z = (v[w].z - mean) * rstd;
        r.w = (v[w].w - mean) * rstd;
        *(float4*)(op + w*128 + lane*4) = r;
    }
}

// ---------------- fc2_gemm: X2 = h @ W2 + b2 + Xn ----------------
// M=1024, N=1280, K=128. grid (16, 20), BM=BN=64, BK=16.
__global__ void fc2_gemm(const float* __restrict__ h, const float* __restrict__ W2,
                         const float* __restrict__ b2, const float* __restrict__ Xn,
                         float* __restrict__ X2) {
    __shared__ __align__(16) float As[16][68];
    __shared__ __align__(16) float Bs[16][64];
    const int tid = threadIdx.x;
    const int tx = tid & 15;
    const int ty = tid >> 4;
    const int m0 = blockIdx.x * 64;
    const int n0 = blockIdx.y * 64;

    const int a_kc = tid & 3;
    const int a_m  = tid >> 2;
    const int b_c = tid & 15;
    const int b_r = tid >> 4;

    const float* Ap = h  + (size_t)(m0 + a_m) * NH + a_kc * 4;
    const float* Bp = W2 + (size_t)b_r * NV + n0 + b_c * 4;

    float4 ra = *(const float4*)Ap;
    float4 rb = *(const float4*)Bp;

    float acc[4][4] = {};

    const int NTILES = NH / 16;   // 8
    for (int t = 0; t < NTILES; t++) {
        As[a_kc*4+0][a_m] = ra.x;
        As[a_kc*4+1][a_m] = ra.y;
        As[a_kc*4+2][a_m] = ra.z;
        As[a_kc*4+3][a_m] = ra.w;
        *(float4*)&Bs[b_r][b_c*4] = rb;
        __syncthreads();

        if (t + 1 < NTILES) {
            ra = *(const float4*)(Ap + (t+1)*16);
            rb = *(const float4*)(Bp + (size_t)(t+1)*16*NV);
        }

#pragma unroll
        for (int kk = 0; kk < 16; kk++) {
            float4 av = *(const float4*)&As[kk][ty*4];
            float4 bv = *(const float4*)&Bs[kk][tx*4];
            acc[0][0] += av.x*bv.x; acc[0][1] += av.x*bv.y; acc[0][2] += av.x*bv.z; acc[0][3] += av.x*bv.w;
            acc[1][0] += av.y*bv.x; acc[1][1] += av.y*bv.y; acc[1][2] += av.y*bv.z; acc[1][3] += av.y*bv.w;
            acc[2][0] += av.z*bv.x; acc[2][1] += av.z*bv.y; acc[2][2] += av.z*bv.z; acc[2][3] += av.z*bv.w;
            acc[3][0] += av.w*bv.x; acc[3][1] += av.w*bv.y; acc[3][2] += av.w*bv.z; acc[3][3] += av.w*bv.w;
        }
        __syncthreads();
    }

    const float4 bias = *(const float4*)&b2[n0 + tx*4];
#pragma unroll
    for (int i = 0; i < 4; i++) {
        int row = m0 + ty*4 + i;
        const float4 xr = *(const float4*)&Xn[(size_t)row * NV + n0 + tx*4];
        float4 v = make_float4(acc[i][0] + bias.x + xr.x, acc[i][1] + bias.y + xr.y,
                               acc[i][2] + bias.z + xr.z, acc[i][3] + bias.w + xr.w);
        *(float4*)&X2[(size_t)row * NV + n0 + tx*4] = v;
    }
}

// ---------------- final: lys-row attention + LN + head MLP ----------------
__global__ void final_kernel(const float* __restrict__ X, const float* __restrict__ k4T,
                             const float* __restrict__ Wq4, const float* __restrict__ wv4,
                             const int* __restrict__ lys_pos,
                             const float* __restrict__ hW1, const float* __restrict__ hb1,
                             const float* __restrict__ hW2, const float* __restrict__ hb2,
                             const float* __restrict__ hW3, const float* __restrict__ hb3,
                             float* __restrict__ out) {
    __shared__ float xl[NV];
    __shared__ float q4[NH];
    __shared__ float sp[NS];
    __shared__ float swv[NH];
    __shared__ float red[32];
    __shared__ float h1s[32];
    __shared__ float h2s[12];
    __shared__ float stats[2];

    const int b = blockIdx.x, tid = threadIdx.x;
    const int wid = tid >> 5, lane = tid & 31;
    const int lp = *lys_pos;

    const float* xrow = X + (size_t)(b*NS + lp) * NV;
    for (int v = tid; v < NV; v += 256) xl[v] = xrow[v];
    if (tid < NH) swv[tid] = wv4[tid];
    __syncthreads();

    if (tid < NH) {
        float s = 0.f;
        for (int v = 0; v < NV; v++) s += xl[v] * Wq4[(size_t)v * NH + tid];
        q4[tid] = s;
    }
    __syncthreads();

    {
        float s = 0.f;
        const float* kp = k4T + (size_t)(b*NH) * NS + tid;
        for (int h = 0; h < NH; h++) s += swv[h] * tanh_fast(q4[h] + kp[(size_t)h * NS]);
        sp[tid] = s;
    }
    __syncthreads();

    float sv = sp[tid];
    float m = sv;
#pragma unroll
    for (int o = 16; o; o >>= 1) m = fmaxf(m, __shfl_xor_sync(0xffffffffu, m, o));
    if (lane == 0) red[wid] = m;
    __syncthreads();
    if (tid == 0) {
        float t = red[0];
        for (int w = 1; w < 8; w++) t = fmaxf(t, red[w]);
        red[8] = t;
    }
    __syncthreads();
    m = red[8];
    float e = __expf(sv - m);
    float ssum = e;
#pragma unroll
    for (int o = 16; o; o >>= 1) ssum += __shfl_xor_sync(0xffffffffu, ssum, o);
    if (lane == 0) red[16 + wid] = ssum;
    __syncthreads();
    if (tid == 0) {
        float t = 0.f;
        for (int w = 0; w < 8; w++) t += red[16 + w];
        red[24] = 1.f / t;
    }
    __syncthreads();
    sp[tid] = e * red[24];
    __syncthreads();

    float4 o4 = make_float4(xl[tid*4], xl[tid*4+1], xl[tid*4+2], xl[tid*4+3]);
    float o1 = xl[1024 + tid];
    for (int jj = 0; jj < NS; jj++) {
        const float* xp = X + (size_t)(b*NS + jj) * NV;
        float4 xv = *(const float4*)(xp + tid*4);
        float pj = sp[jj];
        o4.x += pj*xv.x; o4.y += pj*xv.y; o4.z += pj*xv.z; o4.w += pj*xv.w;
        o1 += pj*xp[1024 + tid];
    }

    float s1 = o4.x + o4.y + o4.z + o4.w + o1;
    float s2 = o4.x*o4.x + o4.y*o4.y + o4.z*o4.z + o4.w*o4.w + o1*o1;
#pragma unroll
    for (int of = 16; of; of >>= 1) {
        s1 += __shfl_xor_sync(0xffffffffu, s1, of);
        s2 += __shfl_xor_sync(0xffffffffu, s2, of);
    }
    if (lane == 0) { red[wid] = s1; red[8 + wid] = s2; }
    __syncthreads();
    if (tid == 0) {
        float a = 0.f, bsq = 0.f;
        for (int w = 0; w < 8; w++) { a += red[w]; bsq += red[8 + w]; }
        float mean = a * (1.f / NV);
        float var  = bsq * (1.f / NV) - mean*mean;
        stats[0] = mean;
        stats[1] = rsqrtf(var + EPSV);
    }
    __syncthreads();
    {
        float mean = stats[0], rstd = stats[1];
        xl[tid*4+0] = (o4.x - mean) * rstd;
        xl[tid*4+1] = (o4.y - mean) * rstd;
        xl[tid*4+2] = (o4.z - mean) * rstd;
        xl[tid*4+3] = (o4.w - mean) * rstd;
        xl[1024 + tid] = (o1 - mean) * rstd;
    }
    __syncthreads();

    if (tid < 32) {
        float s = hb1[tid];
        for (int v = 0; v < NV; v++) s += xl[v] * hW1[(size_t)v * 32 + tid];
        h1s[tid] = fmaxf(s, 0.f);
    }
    __syncthreads();
    if (tid < 12) {
        float s = hb2[tid];
        for (int u = 0; u < 32; u++) s += h1s[u] * hW2[u*12 + tid];
        h2s[tid] = fmaxf(s, 0.f);
    }
    __syncthreads();
    if (tid < 2) {
        float s = hb3[tid];
        for (int u = 0; u < 12; u++) s += h2s[u] * hW3[u*2 + tid];
        out[b*2 + tid] = s;
    }
}

// ---------------- launch ----------------
extern "C" void kernel_launch(void* const* d_in, const int* in_sizes, int n_in,
                              void* d_out, int out_size) {
    const float* X   = (const float*)d_in[0];
    const int*   lys = (const int*)  d_in[1];
    const float* Wq[4]  = {(const float*)d_in[2],  (const float*)d_in[5],
                           (const float*)d_in[8],  (const float*)d_in[11]};
    const float* Wk[4]  = {(const float*)d_in[3],  (const float*)d_in[6],
                           (const float*)d_in[9],  (const float*)d_in[12]};
    const float* wv[4]  = {(const float*)d_in[4],  (const float*)d_in[7],
                           (const float*)d_in[10], (const float*)d_in[13]};
    const float* rW1[3] = {(const float*)d_in[14], (const float*)d_in[18], (const float*)d_in[22]};
    const float* rb1[3] = {(const float*)d_in[15], (const float*)d_in[19], (const float*)d_in[23]};
    const float* rW2[3] = {(const float*)d_in[16], (const float*)d_in[20], (const float*)d_in[24]};
    const float* rb2[3] = {(const float*)d_in[17], (const float*)d_in[21], (const float*)d_in[25]};
    const float* hW1 = (const float*)d_in[26];
    const float* hb1 = (const float*)d_in[27];
    const float* hW2 = (const float*)d_in[28];
    const float* hb2 = (const float*)d_in[29];
    const float* hW3 = (const float*)d_in[30];
    const float* hb3 = (const float*)d_in[31];
    float* out = (float*)d_out;

    float *q, *kT, *Xn, *h, *X2, *Y, *S, *P;
    cudaGetSymbolAddress((void**)&q,  g_q);
    cudaGetSymbolAddress((void**)&kT, g_kT);
    cudaGetSymbolAddress((void**)&Xn, g_Xn);
    cudaGetSymbolAddress((void**)&h,  g_h);
    cudaGetSymbolAddress((void**)&X2, g_X2);
    cudaGetSymbolAddress((void**)&Y,  g_Y);
    cudaGetSymbolAddress((void**)&S,  g_S);
    cudaGetSymbolAddress((void**)&P,  g_P);

    const float* cur = X;
    for (int l = 0; l < 3; l++) {
        gemm_splitk<2><<<dim3(16, 4, SPLITS), 256>>>(cur, Wq[l], Wk[l], P);
        epi_qk<<<256, 256>>>(P, q, kT);
        score_softmax<<<NROWS/8, 256>>>(q, kT, wv[l], S);
        av_gemm<<<dim3(4, 20, NB), 256>>>(S, cur, Y);
        ln_rows<<<NROWS/8, 256>>>(Y, Xn);
        gemm_splitk<1><<<dim3(16, 2, SPLITS), 256>>>(Xn, rW1[l], nullptr, P);
        epi_bias_relu<<<128, 256>>>(P, rb1[l], h);
        fc2_gemm<<<dim3(16, 20), 256>>>(h, rW2[l], rb2[l], Xn, X2);
        cur = X2;
    }
    gemm_splitk<1><<<dim3(16, 2, SPLITS), 256>>>(cur, Wk[3], nullptr, P);
    epi_ktrans<<<128, 256>>>(P, kT);
    final_kernel<<<NB, 256>>>(cur, kT, Wq[3], wv[3], lys,
                              hW1, hb1, hW2, hb2, hW3, hb3, out);
}